// round 4
// baseline (speedup 1.0000x reference)
#include <cuda_runtime.h>
#include <cstdint>

// Problem constants
#define Bb 32
#define Cc 64
#define Lc 8192
#define Mm (Bb * Lc)            // 262144 columns
#define NBLK 512                // gram/apply blocks (each handles 512 columns)
#define EPSV 1e-5f

// ---------------- scratch (device globals; no allocation allowed) ----------------
__device__ __align__(16) float g_gram_part[NBLK * 4096];   // 8 MB partial Grams
__device__ __align__(16) float g_sum_part[NBLK * 64];
__device__ __align__(16) float g_gram[4096];
__device__ __align__(16) float g_mean[64];
__device__ __align__(16) float g_wmT[4096];                // wmT[cp][c] = wm[c][cp]
__device__ __align__(16) float g_bias[64];                 // wm @ mean

// ---------------- f32x2 helpers (FFMA2: 2x fp32 FMA throughput) ----------------
__device__ __forceinline__ unsigned long long dup2(float v) {
    unsigned long long r;
    asm("mov.b64 %0, {%1, %1};" : "=l"(r) : "f"(v));
    return r;
}
__device__ __forceinline__ void fma2(unsigned long long& d, unsigned long long a,
                                     unsigned long long b) {
    asm("fma.rn.f32x2 %0, %1, %2, %0;" : "+l"(d) : "l"(a), "l"(b));
}
__device__ __forceinline__ float2 unpk(unsigned long long v) {
    float2 r;
    asm("mov.b64 {%0, %1}, %2;" : "=f"(r.x), "=f"(r.y) : "l"(v));
    return r;
}

// ================= Kernel 1: per-block partial Gram + channel sums =================
// Grid 512: block = (batch b, 512-column chunk). 8 inner tiles of 64 columns.
// Tile stored transposed in smem as sT[k][c] (row stride 68) so both MMA operands
// are contiguous vector loads.
__global__ __launch_bounds__(256) void gram_kernel(const float* __restrict__ X) {
    __shared__ __align__(16) float sT[64 * 68];
    const int tid = threadIdx.x;
    const int bid = blockIdx.x;
    const int b  = bid >> 4;
    const int l0 = (bid & 15) << 9;                 // 512 columns per block
    const float* Xb = X + (size_t)b * Cc * Lc;

    const int ty = tid >> 4, tx = tid & 15;
    const int r  = ty * 4;                          // output rows   (channel c1)
    const int cc = tx * 4;                          // output cols   (channel c2)

    unsigned long long acc[4][2] = {};
    float csum = 0.f;

    for (int t = 0; t < 8; t++) {
        const int l = l0 + t * 64;
        // load 64c x 64k tile, transposed into sT[k][c]
        #pragma unroll
        for (int it = 0; it < 4; it++) {
            int p = it * 256 + tid;
            int c = p >> 4, k4 = p & 15;
            float4 v = *(const float4*)&Xb[c * Lc + l + k4 * 4];
            int kb = k4 * 4;
            sT[(kb + 0) * 68 + c] = v.x;
            sT[(kb + 1) * 68 + c] = v.y;
            sT[(kb + 2) * 68 + c] = v.z;
            sT[(kb + 3) * 68 + c] = v.w;
        }
        __syncthreads();

        // channel sums (threads 0..63, conflict-free consecutive reads)
        if (tid < 64) {
            #pragma unroll 16
            for (int k = 0; k < 64; k++) csum += sT[k * 68 + tid];
        }

        // rank-64 update of the 64x64 Gram, FFMA2 inner loop
        #pragma unroll 8
        for (int k = 0; k < 64; k++) {
            float4 a4 = *(const float4*)&sT[k * 68 + r];
            ulonglong2 b2 = *(const ulonglong2*)&sT[k * 68 + cc];
            unsigned long long a;
            a = dup2(a4.x); fma2(acc[0][0], a, b2.x); fma2(acc[0][1], a, b2.y);
            a = dup2(a4.y); fma2(acc[1][0], a, b2.x); fma2(acc[1][1], a, b2.y);
            a = dup2(a4.z); fma2(acc[2][0], a, b2.x); fma2(acc[2][1], a, b2.y);
            a = dup2(a4.w); fma2(acc[3][0], a, b2.x); fma2(acc[3][1], a, b2.y);
        }
        __syncthreads();
    }

    float* gp = g_gram_part + (size_t)bid * 4096;
    #pragma unroll
    for (int i = 0; i < 4; i++) {
        float2 p0 = unpk(acc[i][0]), p1 = unpk(acc[i][1]);
        *(float4*)&gp[(r + i) * 64 + cc] = make_float4(p0.x, p0.y, p1.x, p1.y);
    }
    if (tid < 64) g_sum_part[bid * 64 + tid] = csum;
}

// ================= Kernel 2: deterministic reduction of partials =================
__global__ void reduce_kernel() {
    const int tid = threadIdx.x;
    if (blockIdx.x < 16) {
        const int e = blockIdx.x * 256 + tid;
        float a0 = 0.f, a1 = 0.f, a2 = 0.f, a3 = 0.f;
        for (int p = 0; p < NBLK; p += 4) {
            a0 += g_gram_part[(size_t)(p + 0) * 4096 + e];
            a1 += g_gram_part[(size_t)(p + 1) * 4096 + e];
            a2 += g_gram_part[(size_t)(p + 2) * 4096 + e];
            a3 += g_gram_part[(size_t)(p + 3) * 4096 + e];
        }
        g_gram[e] = (a0 + a1) + (a2 + a3);
    } else if (tid < 64) {
        float a0 = 0.f, a1 = 0.f, a2 = 0.f, a3 = 0.f;
        for (int p = 0; p < NBLK; p += 4) {
            a0 += g_sum_part[(p + 0) * 64 + tid];
            a1 += g_sum_part[(p + 1) * 64 + tid];
            a2 += g_sum_part[(p + 2) * 64 + tid];
            a3 += g_sum_part[(p + 3) * 64 + tid];
        }
        g_mean[tid] = ((a0 + a1) + (a2 + a3)) * (1.0f / (float)Mm);
    }
}

// ================= Kernel 3: Sigma + Newton-Schulz (single block) =================
__device__ __align__(16) float dummy_keep;  // (nothing)

__device__ __forceinline__ void mm64(const float* A, const float* Bm, float* Cm, int tid) {
    const int ty = tid >> 4, tx = tid & 15;
    const int r = ty * 4, cb = tx * 4;
    unsigned long long acc[4][2] = {};
    #pragma unroll 8
    for (int k = 0; k < 64; k++) {
        ulonglong2 b2 = *(const ulonglong2*)&Bm[k * 64 + cb];
        #pragma unroll
        for (int i = 0; i < 4; i++) {
            unsigned long long a = dup2(A[(r + i) * 64 + k]);
            fma2(acc[i][0], a, b2.x);
            fma2(acc[i][1], a, b2.y);
        }
    }
    __syncthreads();   // all reads done before any write (C may alias A/B)
    #pragma unroll
    for (int i = 0; i < 4; i++) {
        float2 p0 = unpk(acc[i][0]), p1 = unpk(acc[i][1]);
        *(float4*)&Cm[(r + i) * 64 + cb] = make_float4(p0.x, p0.y, p1.x, p1.y);
    }
    __syncthreads();
}

__global__ __launch_bounds__(256) void solver_kernel() {
    __shared__ __align__(16) float P[4096];
    __shared__ __align__(16) float S[4096];
    __shared__ __align__(16) float T1[4096];
    const int tid = threadIdx.x;
    const float inv_m = 1.0f / (float)Mm;

    // Sigma = eps*I + G/m - mean*mean^T
    for (int e = tid; e < 4096; e += 256) {
        int c1 = e >> 6, c2 = e & 63;
        S[e] = g_gram[e] * inv_m - g_mean[c1] * g_mean[c2] + ((c1 == c2) ? EPSV : 0.0f);
    }
    __syncthreads();

    // every thread computes the trace (broadcast reads; bitwise identical)
    float tr = 0.f;
    #pragma unroll
    for (int c = 0; c < 64; c++) tr += S[c * 65];
    const float rTr = 1.0f / tr;
    __syncthreads();

    for (int e = tid; e < 4096; e += 256) {
        S[e] *= rTr;
        int c1 = e >> 6, c2 = e & 63;
        P[e] = (c1 == c2) ? 1.0f : 0.0f;
    }
    __syncthreads();

    // 5 Newton-Schulz iterations: P = 1.5P - 0.5*(P@P@P)@S
    for (int it = 0; it < 5; it++) {
        mm64(P, P, T1, tid);   // T1 = P^2
        mm64(T1, P, T1, tid);  // T1 = P^3
        mm64(T1, S, T1, tid);  // T1 = P^3 @ SigmaN
        for (int e = tid; e < 4096; e += 256)
            P[e] = 1.5f * P[e] - 0.5f * T1[e];
        __syncthreads();
    }

    const float sq = sqrtf(rTr);
    // store wm transposed for the apply kernel, and bias = wm @ mean
    for (int e = tid; e < 4096; e += 256) {
        int c = e >> 6, cp = e & 63;
        g_wmT[cp * 64 + c] = P[e] * sq;
    }
    if (tid < 64) {
        float bsum = 0.f;
        #pragma unroll 8
        for (int cp = 0; cp < 64; cp++) bsum += P[tid * 64 + cp] * g_mean[cp];
        g_bias[tid] = bsum * sq;
    }
}

// ================= Kernel 4: apply  Y = wm @ X - bias =================
__global__ __launch_bounds__(256) void apply_kernel(const float* __restrict__ X,
                                                    float* __restrict__ Y) {
    __shared__ __align__(16) float s_w[4096];   // wmT[cp][c]
    __shared__ __align__(16) float s_x[4096];   // x tile [cp][j]
    __shared__ float s_b[64];
    const int tid = threadIdx.x;

    for (int e = tid; e < 4096; e += 256) s_w[e] = g_wmT[e];
    if (tid < 64) s_b[tid] = g_bias[tid];

    const int bid = blockIdx.x;
    const int b  = bid >> 4;
    const int l0 = (bid & 15) << 9;
    const float* Xb = X + (size_t)b * Cc * Lc;
    float* Yb = Y + (size_t)b * Cc * Lc;

    const int ty = tid >> 4, tx = tid & 15;
    const int r = ty * 4, jj = tx * 4;
    __syncthreads();

    for (int t = 0; t < 8; t++) {
        const int l = l0 + t * 64;
        #pragma unroll
        for (int it = 0; it < 4; it++) {
            int p = it * 256 + tid;
            int c = p >> 4, k4 = p & 15;
            *(float4*)&s_x[c * 64 + k4 * 4] = *(const float4*)&Xb[c * Lc + l + k4 * 4];
        }
        __syncthreads();

        unsigned long long acc[4][2] = {};
        #pragma unroll 8
        for (int k = 0; k < 64; k++) {
            float4 a4 = *(const float4*)&s_w[k * 64 + r];
            ulonglong2 b2 = *(const ulonglong2*)&s_x[k * 64 + jj];
            unsigned long long a;
            a = dup2(a4.x); fma2(acc[0][0], a, b2.x); fma2(acc[0][1], a, b2.y);
            a = dup2(a4.y); fma2(acc[1][0], a, b2.x); fma2(acc[1][1], a, b2.y);
            a = dup2(a4.z); fma2(acc[2][0], a, b2.x); fma2(acc[2][1], a, b2.y);
            a = dup2(a4.w); fma2(acc[3][0], a, b2.x); fma2(acc[3][1], a, b2.y);
        }

        #pragma unroll
        for (int i = 0; i < 4; i++) {
            float bb = s_b[r + i];
            float2 p0 = unpk(acc[i][0]), p1 = unpk(acc[i][1]);
            *(float4*)&Yb[(r + i) * Lc + l + jj] =
                make_float4(p0.x - bb, p0.y - bb, p1.x - bb, p1.y - bb);
        }
        __syncthreads();
    }
}

// ================= launch =================
extern "C" void kernel_launch(void* const* d_in, const int* in_sizes, int n_in,
                              void* d_out, int out_size) {
    const float* X = (const float*)d_in[0];
    float* Y = (float*)d_out;

    gram_kernel<<<NBLK, 256>>>(X);
    reduce_kernel<<<17, 256>>>();
    solver_kernel<<<1, 256>>>();
    apply_kernel<<<NBLK, 256>>>(X, Y);
}

// round 5
// speedup vs baseline: 1.1407x; 1.1407x over previous
#include <cuda_runtime.h>
#include <cstdint>

// Problem constants
#define Bb 32
#define Cc 64
#define Lc 8192
#define Mm (Bb * Lc)            // 262144 columns
#define NBLK_G 512              // gram blocks (512 columns each)
#define NBLK_A 1024             // apply blocks (256 columns each)
#define EPSV 1e-5f

// ---------------- scratch (device globals; no allocation allowed) ----------------
__device__ __align__(16) float g_gram_part[NBLK_G * 4096];   // 8 MB partial Grams
__device__ __align__(16) float g_sum_part[NBLK_G * 64];
__device__ __align__(16) float g_gram[4096];
__device__ __align__(16) float g_mean[64];
__device__ __align__(16) float g_wmT[4096];                  // wmT[k][c] = wm[c][k]
__device__ __align__(16) float g_bias[64];                   // wm @ mean

// ---------------- f32x2 helpers (FFMA2: 2x fp32 FMA throughput) ----------------
__device__ __forceinline__ unsigned long long dup2(float v) {
    unsigned long long r;
    asm("mov.b64 %0, {%1, %1};" : "=l"(r) : "f"(v));
    return r;
}
__device__ __forceinline__ void fma2(unsigned long long& d, unsigned long long a,
                                     unsigned long long b) {
    asm("fma.rn.f32x2 %0, %1, %2, %0;" : "+l"(d) : "l"(a), "l"(b));
}
__device__ __forceinline__ void add2(unsigned long long& d, unsigned long long a) {
    asm("add.rn.f32x2 %0, %0, %1;" : "+l"(d) : "l"(a));
}
__device__ __forceinline__ float2 unpk(unsigned long long v) {
    float2 r;
    asm("mov.b64 {%0, %1}, %2;" : "=f"(r.x), "=f"(r.y) : "l"(v));
    return r;
}

// 8-row x 8-col FFMA2 micro-tile: a0/a1 = 8 A scalars, b0/b1 = 4 B pairs
#define MICRO_FMA_ROW(ACC, AV)                                          \
    do { unsigned long long _d = dup2(AV);                              \
         fma2(ACC[0], _d, b0.x); fma2(ACC[1], _d, b0.y);                \
         fma2(ACC[2], _d, b1.x); fma2(ACC[3], _d, b1.y); } while (0)

// ================= Kernel 1: per-block partial Gram + channel sums =================
// Grid 512: block = (batch b, 512-column chunk), 8 tiles of 64 columns.
// Split-k in block: 4 groups x 64 threads; group g handles k = g*16 .. g*16+15
// of each tile with an 8x8 register tile; partials reduced through smem.
__global__ __launch_bounds__(256, 2) void gram_kernel(const float* __restrict__ X) {
    __shared__ __align__(16) float sT[64 * 68];                 // [k][c], stride 68
    __shared__ __align__(16) unsigned long long red2[2048];    // 16 KB reduce buffer
    const int tid = threadIdx.x;
    const int bid = blockIdx.x;
    const int b  = bid >> 4;
    const int l0 = (bid & 15) << 9;
    const float* Xb = X + (size_t)b * Cc * Lc;

    const int g  = tid >> 6;            // split-k group 0..3
    const int gt = tid & 63;
    const int gy = gt >> 3, gx = gt & 7;
    const int r  = gy * 8;              // 8 output rows
    const int cc = gx * 8;              // 8 output cols
    const int kbase = g * 16;

    unsigned long long acc[8][4];
    #pragma unroll
    for (int i = 0; i < 8; i++)
        #pragma unroll
        for (int j = 0; j < 4; j++) acc[i][j] = 0ull;
    float csum = 0.f;

    #pragma unroll 1
    for (int t = 0; t < 8; t++) {
        const int l = l0 + t * 64;
        // transposed load of 64c x 64k tile into sT[k][c]
        #pragma unroll
        for (int it = 0; it < 4; it++) {
            int p = it * 256 + tid;
            int c = p >> 4, k4 = p & 15;
            float4 v = *(const float4*)&Xb[(size_t)c * Lc + l + k4 * 4];
            int kb = k4 * 4;
            sT[(kb + 0) * 68 + c] = v.x;
            sT[(kb + 1) * 68 + c] = v.y;
            sT[(kb + 2) * 68 + c] = v.z;
            sT[(kb + 3) * 68 + c] = v.w;
        }
        __syncthreads();

        // channel sums (threads 0..63, conflict-free consecutive reads)
        if (tid < 64) {
            #pragma unroll 16
            for (int k = 0; k < 64; k++) csum += sT[k * 68 + tid];
        }

        // this group's 16 k-steps, 8x8 tile
        #pragma unroll
        for (int kk = 0; kk < 16; kk++) {
            const float* row = &sT[(kbase + kk) * 68];
            float4 a0 = *(const float4*)&row[r];
            float4 a1 = *(const float4*)&row[r + 4];
            ulonglong2 b0 = *(const ulonglong2*)&row[cc];
            ulonglong2 b1 = *(const ulonglong2*)&row[cc + 4];
            MICRO_FMA_ROW(acc[0], a0.x);
            MICRO_FMA_ROW(acc[1], a0.y);
            MICRO_FMA_ROW(acc[2], a0.z);
            MICRO_FMA_ROW(acc[3], a0.w);
            MICRO_FMA_ROW(acc[4], a1.x);
            MICRO_FMA_ROW(acc[5], a1.y);
            MICRO_FMA_ROW(acc[6], a1.z);
            MICRO_FMA_ROW(acc[7], a1.w);
        }
        __syncthreads();
    }

    // cross-group reduction (deterministic, sequential rounds)
    #pragma unroll 1
    for (int gg = 1; gg < 4; gg++) {
        if (g == gg) {
            #pragma unroll
            for (int i = 0; i < 8; i++) {
                unsigned long long* dst = &red2[(r + i) * 32 + gx * 4];
                dst[0] = acc[i][0]; dst[1] = acc[i][1];
                dst[2] = acc[i][2]; dst[3] = acc[i][3];
            }
        }
        __syncthreads();
        if (g == 0) {
            #pragma unroll
            for (int i = 0; i < 8; i++) {
                const unsigned long long* src = &red2[(r + i) * 32 + gx * 4];
                add2(acc[i][0], src[0]); add2(acc[i][1], src[1]);
                add2(acc[i][2], src[2]); add2(acc[i][3], src[3]);
            }
        }
        __syncthreads();
    }

    if (g == 0) {
        float* gp = g_gram_part + (size_t)bid * 4096;
        #pragma unroll
        for (int i = 0; i < 8; i++) {
            float2 p0 = unpk(acc[i][0]), p1 = unpk(acc[i][1]);
            float2 p2 = unpk(acc[i][2]), p3 = unpk(acc[i][3]);
            *(float4*)&gp[(r + i) * 64 + cc]     = make_float4(p0.x, p0.y, p1.x, p1.y);
            *(float4*)&gp[(r + i) * 64 + cc + 4] = make_float4(p2.x, p2.y, p3.x, p3.y);
        }
    }
    if (tid < 64) g_sum_part[bid * 64 + tid] = csum;
}

// ================= Kernel 2: deterministic reduction of partials =================
__global__ void reduce_kernel() {
    const int tid = threadIdx.x;
    if (blockIdx.x < 16) {
        const int e = blockIdx.x * 256 + tid;
        float a0 = 0.f, a1 = 0.f, a2 = 0.f, a3 = 0.f;
        for (int p = 0; p < NBLK_G; p += 4) {
            a0 += g_gram_part[(size_t)(p + 0) * 4096 + e];
            a1 += g_gram_part[(size_t)(p + 1) * 4096 + e];
            a2 += g_gram_part[(size_t)(p + 2) * 4096 + e];
            a3 += g_gram_part[(size_t)(p + 3) * 4096 + e];
        }
        g_gram[e] = (a0 + a1) + (a2 + a3);
    } else if (tid < 64) {
        float a0 = 0.f, a1 = 0.f, a2 = 0.f, a3 = 0.f;
        for (int p = 0; p < NBLK_G; p += 4) {
            a0 += g_sum_part[(p + 0) * 64 + tid];
            a1 += g_sum_part[(p + 1) * 64 + tid];
            a2 += g_sum_part[(p + 2) * 64 + tid];
            a3 += g_sum_part[(p + 3) * 64 + tid];
        }
        g_mean[tid] = ((a0 + a1) + (a2 + a3)) * (1.0f / (float)Mm);
    }
}

// ================= Kernel 3: Sigma + Newton-Schulz (single block) =================
__device__ __forceinline__ void mm64(const float* A, const float* Bm, float* Cm, int tid) {
    const int ty = tid >> 4, tx = tid & 15;
    const int r = ty * 4, cb = tx * 4;
    unsigned long long acc[4][2] = {};
    #pragma unroll 8
    for (int k = 0; k < 64; k++) {
        ulonglong2 b2 = *(const ulonglong2*)&Bm[k * 64 + cb];
        #pragma unroll
        for (int i = 0; i < 4; i++) {
            unsigned long long a = dup2(A[(r + i) * 64 + k]);
            fma2(acc[i][0], a, b2.x);
            fma2(acc[i][1], a, b2.y);
        }
    }
    __syncthreads();   // all reads done before any write (C may alias A/B)
    #pragma unroll
    for (int i = 0; i < 4; i++) {
        float2 p0 = unpk(acc[i][0]), p1 = unpk(acc[i][1]);
        *(float4*)&Cm[(r + i) * 64 + cb] = make_float4(p0.x, p0.y, p1.x, p1.y);
    }
    __syncthreads();
}

__global__ __launch_bounds__(256) void solver_kernel() {
    __shared__ __align__(16) float P[4096];
    __shared__ __align__(16) float S[4096];
    __shared__ __align__(16) float T1[4096];
    const int tid = threadIdx.x;
    const float inv_m = 1.0f / (float)Mm;

    // Sigma = eps*I + G/m - mean*mean^T
    for (int e = tid; e < 4096; e += 256) {
        int c1 = e >> 6, c2 = e & 63;
        S[e] = g_gram[e] * inv_m - g_mean[c1] * g_mean[c2] + ((c1 == c2) ? EPSV : 0.0f);
    }
    __syncthreads();

    // every thread computes the trace (broadcast reads; bitwise identical)
    float tr = 0.f;
    #pragma unroll
    for (int c = 0; c < 64; c++) tr += S[c * 65];
    const float rTr = 1.0f / tr;
    __syncthreads();

    for (int e = tid; e < 4096; e += 256) {
        S[e] *= rTr;
        int c1 = e >> 6, c2 = e & 63;
        P[e] = (c1 == c2) ? 1.0f : 0.0f;
    }
    __syncthreads();

    // 5 Newton-Schulz iterations: P = 1.5P - 0.5*(P@P@P)@S
    for (int it = 0; it < 5; it++) {
        mm64(P, P, T1, tid);   // T1 = P^2
        mm64(T1, P, T1, tid);  // T1 = P^3
        mm64(T1, S, T1, tid);  // T1 = P^3 @ SigmaN
        for (int e = tid; e < 4096; e += 256)
            P[e] = 1.5f * P[e] - 0.5f * T1[e];
        __syncthreads();
    }

    const float sq = sqrtf(rTr);
    // store wm transposed (k-major) for the apply kernel, and bias = wm @ mean
    for (int e = tid; e < 4096; e += 256) {
        int c = e >> 6, cp = e & 63;
        g_wmT[cp * 64 + c] = P[e] * sq;
    }
    if (tid < 64) {
        float bsum = 0.f;
        #pragma unroll 8
        for (int cp = 0; cp < 64; cp++) bsum += P[tid * 64 + cp] * g_mean[cp];
        g_bias[tid] = bsum * sq;
    }
}

// ================= Kernel 4: apply  Y = wm @ X - bias =================
// Grid 1024: block = (batch, 256-column tile). 256 threads, 8x8 per-thread tile:
// warp w owns rows w*8..w*8+7 (A loads are warp-broadcast), lane owns cols
// lane*4..+3 and 128+lane*4..+3 (contiguous LDS.128).
#define APPLY_SMEM ((4096 + 16384 + 64) * (int)sizeof(float))

__global__ __launch_bounds__(256, 2) void apply_kernel(const float* __restrict__ X,
                                                       float* __restrict__ Y) {
    extern __shared__ float sm[];
    float* s_w = sm;                 // wmT[k][c]   (16 KB)
    float* s_x = sm + 4096;          // x[k][j]     (64 KB)
    float* s_b = sm + 4096 + 16384;  // bias        (256 B)
    const int tid = threadIdx.x;
    const int bid = blockIdx.x;
    const int b  = bid >> 5;
    const int l0 = (bid & 31) << 8;
    const float* Xb = X + (size_t)b * Cc * Lc;
    float* Yb = Y + (size_t)b * Cc * Lc;

    #pragma unroll
    for (int e = tid; e < 4096; e += 256) s_w[e] = g_wmT[e];
    if (tid < 64) s_b[tid] = g_bias[tid];

    // load 64 x 256 x tile (x is k-major in smem: s_x[k*256 + j])
    #pragma unroll
    for (int it = 0; it < 16; it++) {
        int p = it * 256 + tid;          // float4 index, 4096 total
        int c = p >> 6, j4 = p & 63;
        *(float4*)&s_x[c * 256 + j4 * 4] =
            *(const float4*)&Xb[(size_t)c * Lc + l0 + j4 * 4];
    }
    __syncthreads();

    const int w = tid >> 5, lane = tid & 31;
    const int r = w * 8, j0 = lane * 4;

    unsigned long long acc[8][4];
    #pragma unroll
    for (int i = 0; i < 8; i++)
        #pragma unroll
        for (int j = 0; j < 4; j++) acc[i][j] = 0ull;

    #pragma unroll 8
    for (int k = 0; k < 64; k++) {
        const float* wr = &s_w[k * 64];
        float4 a0 = *(const float4*)&wr[r];          // broadcast within warp
        float4 a1 = *(const float4*)&wr[r + 4];
        const float* xr = &s_x[k * 256];
        ulonglong2 b0 = *(const ulonglong2*)&xr[j0];
        ulonglong2 b1 = *(const ulonglong2*)&xr[j0 + 128];
        MICRO_FMA_ROW(acc[0], a0.x);
        MICRO_FMA_ROW(acc[1], a0.y);
        MICRO_FMA_ROW(acc[2], a0.z);
        MICRO_FMA_ROW(acc[3], a0.w);
        MICRO_FMA_ROW(acc[4], a1.x);
        MICRO_FMA_ROW(acc[5], a1.y);
        MICRO_FMA_ROW(acc[6], a1.z);
        MICRO_FMA_ROW(acc[7], a1.w);
    }

    #pragma unroll
    for (int i = 0; i < 8; i++) {
        float bb = s_b[r + i];
        float2 p0 = unpk(acc[i][0]), p1 = unpk(acc[i][1]);
        float2 p2 = unpk(acc[i][2]), p3 = unpk(acc[i][3]);
        float* yr = &Yb[(size_t)(r + i) * Lc + l0];
        *(float4*)&yr[j0]       = make_float4(p0.x - bb, p0.y - bb, p1.x - bb, p1.y - bb);
        *(float4*)&yr[j0 + 128] = make_float4(p2.x - bb, p2.y - bb, p3.x - bb, p3.y - bb);
    }
}

// ================= launch =================
extern "C" void kernel_launch(void* const* d_in, const int* in_sizes, int n_in,
                              void* d_out, int out_size) {
    const float* X = (const float*)d_in[0];
    float* Y = (float*)d_out;

    cudaFuncSetAttribute(apply_kernel, cudaFuncAttributeMaxDynamicSharedMemorySize,
                         APPLY_SMEM);

    gram_kernel<<<NBLK_G, 256>>>(X);
    reduce_kernel<<<17, 256>>>();
    solver_kernel<<<1, 256>>>();
    apply_kernel<<<NBLK_A, 256, APPLY_SMEM>>>(X, Y);
}

// round 6
// speedup vs baseline: 1.1886x; 1.0420x over previous
#include <cuda_runtime.h>
#include <cstdint>

// Problem constants
#define Bb 32
#define Cc 64
#define Lc 8192
#define Mm (Bb * Lc)            // 262144 columns
#define NBLK_G 1024             // gram blocks (256 columns each)
#define NBLK_A 1024             // apply blocks (256 columns each)
#define EPSV 1e-5f

// ---------------- scratch (device globals; no allocation allowed) ----------------
__device__ __align__(16) float g_gram_part[NBLK_G * 4096];   // 16 MB partial Grams
__device__ __align__(16) float g_sum_part[NBLK_G * 64];
__device__ __align__(16) float g_gram[4096];
__device__ __align__(16) float g_mean[64];
__device__ __align__(16) float g_wmT[4096];                  // wmT[k][c] = wm[c][k]
__device__ __align__(16) float g_bias[64];                   // wm @ mean

// ---------------- f32x2 helpers (FFMA2: 2x fp32 FMA throughput) ----------------
__device__ __forceinline__ unsigned long long dup2(float v) {
    unsigned long long r;
    asm("mov.b64 %0, {%1, %1};" : "=l"(r) : "f"(v));
    return r;
}
__device__ __forceinline__ void fma2(unsigned long long& d, unsigned long long a,
                                     unsigned long long b) {
    asm("fma.rn.f32x2 %0, %1, %2, %0;" : "+l"(d) : "l"(a), "l"(b));
}
__device__ __forceinline__ void add2(unsigned long long& d, unsigned long long a) {
    asm("add.rn.f32x2 %0, %0, %1;" : "+l"(d) : "l"(a));
}
__device__ __forceinline__ float2 unpk(unsigned long long v) {
    float2 r;
    asm("mov.b64 {%0, %1}, %2;" : "=f"(r.x), "=f"(r.y) : "l"(v));
    return r;
}

// 8-row x 8-col FFMA2 micro-tile row: b0/b1 = 4 B pairs in scope
#define MICRO_FMA_ROW(ACC, AV)                                          \
    do { unsigned long long _d = dup2(AV);                              \
         fma2(ACC[0], _d, b0.x); fma2(ACC[1], _d, b0.y);                \
         fma2(ACC[2], _d, b1.x); fma2(ACC[3], _d, b1.y); } while (0)

#define MICRO_TILE()                                                    \
    do {                                                                \
        MICRO_FMA_ROW(acc[0], a0.x);                                    \
        MICRO_FMA_ROW(acc[1], a0.y);                                    \
        MICRO_FMA_ROW(acc[2], a0.z);                                    \
        MICRO_FMA_ROW(acc[3], a0.w);                                    \
        MICRO_FMA_ROW(acc[4], a1.x);                                    \
        MICRO_FMA_ROW(acc[5], a1.y);                                    \
        MICRO_FMA_ROW(acc[6], a1.z);                                    \
        MICRO_FMA_ROW(acc[7], a1.w);                                    \
    } while (0)

// ================= Kernel 1: per-block partial Gram + channel sums =================
// Grid 1024: block = (batch, 256-col chunk), 4 subtiles of 64 columns,
// DOUBLE-BUFFERED: LDG of tile t+1 issued before compute of tile t; STS to the
// idle buffer after compute; one sync per tile. Split-k: 4 groups x 64 threads,
// group g handles k = g*16..g*16+15 with an 8x8 register tile.
__global__ __launch_bounds__(256, 2) void gram_kernel(const float* __restrict__ X) {
    __shared__ __align__(16) float sT[2][64 * 68];             // [buf][k][c]
    const int tid = threadIdx.x;
    const int bid = blockIdx.x;
    const int b  = bid >> 5;
    const int l0 = (bid & 31) << 8;                            // 256 cols per block
    const float* Xb = X + (size_t)b * Cc * Lc;

    const int crow = tid >> 4;          // 0..15 (c within 16-row band)
    const int k4   = tid & 15;
    const int g  = tid >> 6;            // split-k group 0..3
    const int gt = tid & 63;
    const int gy = gt >> 3, gx = gt & 7;
    const int r  = gy * 8;
    const int cc = gx * 8;
    const int kbase = g * 16;

    unsigned long long acc[8][4];
    #pragma unroll
    for (int i = 0; i < 8; i++) { acc[i][0] = acc[i][1] = acc[i][2] = acc[i][3] = 0ull; }
    float cs[4] = {0.f, 0.f, 0.f, 0.f};

    float4 st[4];
    // prefetch + store tile 0
    #pragma unroll
    for (int it = 0; it < 4; it++) {
        int c = it * 16 + crow;
        st[it] = *(const float4*)&Xb[(size_t)c * Lc + l0 + k4 * 4];
    }
    {
        float* dst = &sT[0][0];
        #pragma unroll
        for (int it = 0; it < 4; it++) {
            float4 v = st[it];
            cs[it] += (v.x + v.y) + (v.z + v.w);
            int c = it * 16 + crow, kb = k4 * 4;
            dst[(kb + 0) * 68 + c] = v.x;
            dst[(kb + 1) * 68 + c] = v.y;
            dst[(kb + 2) * 68 + c] = v.z;
            dst[(kb + 3) * 68 + c] = v.w;
        }
    }
    __syncthreads();

    #pragma unroll 1
    for (int t = 0; t < 4; t++) {
        const int cur = t & 1;
        if (t < 3) {
            const int l = l0 + (t + 1) * 64;
            #pragma unroll
            for (int it = 0; it < 4; it++) {
                int c = it * 16 + crow;
                st[it] = *(const float4*)&Xb[(size_t)c * Lc + l + k4 * 4];
            }
        }
        // compute this group's 16 k-steps from sT[cur]
        const float* buf = &sT[cur][0];
        #pragma unroll
        for (int kk = 0; kk < 16; kk++) {
            const float* row = &buf[(kbase + kk) * 68];
            float4 a0 = *(const float4*)&row[r];
            float4 a1 = *(const float4*)&row[r + 4];
            ulonglong2 b0 = *(const ulonglong2*)&row[cc];
            ulonglong2 b1 = *(const ulonglong2*)&row[cc + 4];
            MICRO_TILE();
        }
        if (t < 3) {
            float* dst = &sT[1 - cur][0];
            #pragma unroll
            for (int it = 0; it < 4; it++) {
                float4 v = st[it];
                cs[it] += (v.x + v.y) + (v.z + v.w);
                int c = it * 16 + crow, kb = k4 * 4;
                dst[(kb + 0) * 68 + c] = v.x;
                dst[(kb + 1) * 68 + c] = v.y;
                dst[(kb + 2) * 68 + c] = v.z;
                dst[(kb + 3) * 68 + c] = v.w;
            }
        }
        __syncthreads();
    }

    // cross-group reduction through smem (aliases dead tile buffers; deterministic)
    unsigned long long* red2 = (unsigned long long*)&sT[0][0];   // 2048 ull = 16 KB
    #pragma unroll 1
    for (int gg = 1; gg < 4; gg++) {
        if (g == gg) {
            #pragma unroll
            for (int i = 0; i < 8; i++) {
                unsigned long long* d = &red2[(r + i) * 32 + gx * 4];
                d[0] = acc[i][0]; d[1] = acc[i][1];
                d[2] = acc[i][2]; d[3] = acc[i][3];
            }
        }
        __syncthreads();
        if (g == 0) {
            #pragma unroll
            for (int i = 0; i < 8; i++) {
                const unsigned long long* s2 = &red2[(r + i) * 32 + gx * 4];
                add2(acc[i][0], s2[0]); add2(acc[i][1], s2[1]);
                add2(acc[i][2], s2[2]); add2(acc[i][3], s2[3]);
            }
        }
        __syncthreads();
    }

    if (g == 0) {
        float* gp = g_gram_part + (size_t)bid * 4096;
        #pragma unroll
        for (int i = 0; i < 8; i++) {
            float2 p0 = unpk(acc[i][0]), p1 = unpk(acc[i][1]);
            float2 p2 = unpk(acc[i][2]), p3 = unpk(acc[i][3]);
            *(float4*)&gp[(r + i) * 64 + cc]     = make_float4(p0.x, p0.y, p1.x, p1.y);
            *(float4*)&gp[(r + i) * 64 + cc + 4] = make_float4(p2.x, p2.y, p3.x, p3.y);
        }
    }

    // channel sums: reduce across the 16 lanes sharing (it, crow) via shfl
    #pragma unroll
    for (int it = 0; it < 4; it++) {
        float v = cs[it];
        v += __shfl_down_sync(0xffffffffu, v, 8, 16);
        v += __shfl_down_sync(0xffffffffu, v, 4, 16);
        v += __shfl_down_sync(0xffffffffu, v, 2, 16);
        v += __shfl_down_sync(0xffffffffu, v, 1, 16);
        if (k4 == 0) g_sum_part[bid * 64 + it * 16 + crow] = v;
    }
}

// ================= Kernel 2: deterministic reduction of partials =================
// 129 blocks. Blocks 0..127: 32 Gram elements each, coalesced over e, 8 MLP chains.
// Block 128: channel sums -> mean.
__global__ __launch_bounds__(256) void reduce_kernel() {
    __shared__ float s[256];
    const int tid = threadIdx.x;
    if (blockIdx.x < 128) {
        const int e = blockIdx.x * 32 + (tid & 31);
        const int chunk = tid >> 5;                        // 0..7, 128 partials each
        const float* base = g_gram_part + (size_t)chunk * 128 * 4096 + e;
        float a0 = 0, a1 = 0, a2 = 0, a3 = 0, a4 = 0, a5 = 0, a6 = 0, a7 = 0;
        #pragma unroll 1
        for (int q = 0; q < 128; q += 8) {
            a0 += base[(size_t)(q + 0) * 4096];
            a1 += base[(size_t)(q + 1) * 4096];
            a2 += base[(size_t)(q + 2) * 4096];
            a3 += base[(size_t)(q + 3) * 4096];
            a4 += base[(size_t)(q + 4) * 4096];
            a5 += base[(size_t)(q + 5) * 4096];
            a6 += base[(size_t)(q + 6) * 4096];
            a7 += base[(size_t)(q + 7) * 4096];
        }
        s[tid] = ((a0 + a1) + (a2 + a3)) + ((a4 + a5) + (a6 + a7));
        __syncthreads();
        if (tid < 32) {
            float r = 0.f;
            #pragma unroll
            for (int ch = 0; ch < 8; ch++) r += s[ch * 32 + tid];
            g_gram[blockIdx.x * 32 + tid] = r;
        }
    } else {
        const int c = tid & 63, chunk = tid >> 6;          // 4 chunks x 256 partials
        const float* base = g_sum_part + (size_t)chunk * 256 * 64 + c;
        float a0 = 0, a1 = 0, a2 = 0, a3 = 0, a4 = 0, a5 = 0, a6 = 0, a7 = 0;
        #pragma unroll 1
        for (int q = 0; q < 256; q += 8) {
            a0 += base[(q + 0) * 64]; a1 += base[(q + 1) * 64];
            a2 += base[(q + 2) * 64]; a3 += base[(q + 3) * 64];
            a4 += base[(q + 4) * 64]; a5 += base[(q + 5) * 64];
            a6 += base[(q + 6) * 64]; a7 += base[(q + 7) * 64];
        }
        s[tid] = ((a0 + a1) + (a2 + a3)) + ((a4 + a5) + (a6 + a7));
        __syncthreads();
        if (tid < 64) {
            float r = (s[tid] + s[64 + tid]) + (s[128 + tid] + s[192 + tid]);
            g_mean[tid] = r * (1.0f / (float)Mm);
        }
    }
}

// ================= Kernel 3: Sigma + Newton-Schulz (single block) =================
// Ping-pong buffers: mm writes a distinct buffer -> one sync per matmul.
__device__ __noinline__ void mm64v(const float* __restrict__ A,
                                   const float* __restrict__ Bm,
                                   float* __restrict__ Cm, int tid) {
    const int ty = tid >> 4, tx = tid & 15;
    const int r = ty * 4, cb = tx * 4;
    unsigned long long acc[4][2] = {};
    #pragma unroll
    for (int k4 = 0; k4 < 16; k4++) {
        float4 a0 = *(const float4*)&A[(r + 0) * 64 + k4 * 4];
        float4 a1 = *(const float4*)&A[(r + 1) * 64 + k4 * 4];
        float4 a2 = *(const float4*)&A[(r + 2) * 64 + k4 * 4];
        float4 a3 = *(const float4*)&A[(r + 3) * 64 + k4 * 4];
        #pragma unroll
        for (int kk = 0; kk < 4; kk++) {
            float f0 = kk == 0 ? a0.x : kk == 1 ? a0.y : kk == 2 ? a0.z : a0.w;
            float f1 = kk == 0 ? a1.x : kk == 1 ? a1.y : kk == 2 ? a1.z : a1.w;
            float f2 = kk == 0 ? a2.x : kk == 1 ? a2.y : kk == 2 ? a2.z : a2.w;
            float f3 = kk == 0 ? a3.x : kk == 1 ? a3.y : kk == 2 ? a3.z : a3.w;
            ulonglong2 b2 = *(const ulonglong2*)&Bm[(k4 * 4 + kk) * 64 + cb];
            unsigned long long d;
            d = dup2(f0); fma2(acc[0][0], d, b2.x); fma2(acc[0][1], d, b2.y);
            d = dup2(f1); fma2(acc[1][0], d, b2.x); fma2(acc[1][1], d, b2.y);
            d = dup2(f2); fma2(acc[2][0], d, b2.x); fma2(acc[2][1], d, b2.y);
            d = dup2(f3); fma2(acc[3][0], d, b2.x); fma2(acc[3][1], d, b2.y);
        }
    }
    #pragma unroll
    for (int i = 0; i < 4; i++) {
        float2 p0 = unpk(acc[i][0]), p1 = unpk(acc[i][1]);
        *(float4*)&Cm[(r + i) * 64 + cb] = make_float4(p0.x, p0.y, p1.x, p1.y);
    }
    __syncthreads();
}

#define SOLVER_SMEM (4 * 4096 * (int)sizeof(float))

__global__ __launch_bounds__(256) void solver_kernel() {
    extern __shared__ float ssm[];
    float* P = ssm;
    float* S = ssm + 4096;
    float* U = ssm + 8192;
    float* V = ssm + 12288;
    const int tid = threadIdx.x;
    const float inv_m = 1.0f / (float)Mm;

    // Sigma = eps*I + G/m - mean*mean^T
    for (int e = tid; e < 4096; e += 256) {
        int c1 = e >> 6, c2 = e & 63;
        S[e] = g_gram[e] * inv_m - g_mean[c1] * g_mean[c2] + ((c1 == c2) ? EPSV : 0.0f);
    }
    __syncthreads();

    // every thread computes the trace (broadcast reads; bitwise identical)
    float tr = 0.f;
    #pragma unroll
    for (int c = 0; c < 64; c++) tr += S[c * 65];
    const float rTr = 1.0f / tr;
    __syncthreads();

    for (int e = tid; e < 4096; e += 256) {
        S[e] *= rTr;
        int c1 = e >> 6, c2 = e & 63;
        P[e] = (c1 == c2) ? 1.0f : 0.0f;
    }
    __syncthreads();

    // 5 Newton-Schulz iterations: P = 1.5P - 0.5*(P@P@P)@S
    #pragma unroll 1
    for (int it = 0; it < 5; it++) {
        mm64v(P, P, U, tid);   // U = P^2
        mm64v(U, P, V, tid);   // V = P^3
        mm64v(V, S, U, tid);   // U = P^3 @ SigmaN
        for (int e = tid; e < 4096; e += 256)
            P[e] = 1.5f * P[e] - 0.5f * U[e];
        __syncthreads();
    }

    const float sq = sqrtf(rTr);
    for (int e = tid; e < 4096; e += 256) {
        int c = e >> 6, cp = e & 63;
        g_wmT[cp * 64 + c] = P[e] * sq;
    }
    if (tid < 64) {
        float bs = 0.f;
        #pragma unroll 8
        for (int cp = 0; cp < 64; cp++) bs += P[tid * 64 + cp] * g_mean[cp];
        g_bias[tid] = bs * sq;
    }
}

// ================= Kernel 4: apply  Y = wm @ X - bias =================
// Grid 1024: block = (batch, 256-col tile), k-split double buffering:
// load k-half 0, LDG k-half 1 into regs (overlaps half-0 compute), then finish.
// 8x8 per-thread tile: warp w owns rows w*8..+7 (broadcast A), lane owns cols
// lane*4..+3 and 128+lane*4..+3 (contiguous LDS.128).
#define APPLY_SMEM ((4096 + 2 * 8192 + 64) * (int)sizeof(float))

__global__ __launch_bounds__(256, 2) void apply_kernel(const float* __restrict__ X,
                                                       float* __restrict__ Y) {
    extern __shared__ float sm[];
    float* s_w  = sm;                    // wmT[k][c]           16 KB
    float* s_x0 = sm + 4096;             // x[k=0..31][256]     32 KB
    float* s_x1 = sm + 12288;            // x[k=32..63][256]    32 KB
    float* s_b  = sm + 20480;            // bias
    const int tid = threadIdx.x;
    const int bid = blockIdx.x;
    const int b  = bid >> 5;
    const int l0 = (bid & 31) << 8;
    const float* Xb = X + (size_t)b * Cc * Lc;
    float* Yb = Y + (size_t)b * Cc * Lc;

    // wm + bias
    #pragma unroll
    for (int it = 0; it < 4; it++) {
        int p = it * 256 + tid;
        *(float4*)&s_w[p * 4] = *(const float4*)&g_wmT[p * 4];
    }
    if (tid < 64) s_b[tid] = g_bias[tid];

    // k-half 0 (c = 0..31)
    #pragma unroll
    for (int it = 0; it < 8; it++) {
        int p = it * 256 + tid;
        int c = p >> 6, j4 = p & 63;
        *(float4*)&s_x0[c * 256 + j4 * 4] =
            *(const float4*)&Xb[(size_t)c * Lc + l0 + j4 * 4];
    }

    // prefetch k-half 1 into regs (overlaps half-0 compute)
    float4 st[8];
    #pragma unroll
    for (int it = 0; it < 8; it++) {
        int p = it * 256 + tid;
        int c = 32 + (p >> 6), j4 = p & 63;
        st[it] = *(const float4*)&Xb[(size_t)c * Lc + l0 + j4 * 4];
    }
    __syncthreads();

    const int w = tid >> 5, lane = tid & 31;
    const int r = w * 8, j0 = lane * 4;

    unsigned long long acc[8][4];
    #pragma unroll
    for (int i = 0; i < 8; i++) { acc[i][0] = acc[i][1] = acc[i][2] = acc[i][3] = 0ull; }

    #pragma unroll 4
    for (int k = 0; k < 32; k++) {
        const float* wr = &s_w[k * 64];
        float4 a0 = *(const float4*)&wr[r];
        float4 a1 = *(const float4*)&wr[r + 4];
        const float* xr = &s_x0[k * 256];
        ulonglong2 b0 = *(const ulonglong2*)&xr[j0];
        ulonglong2 b1 = *(const ulonglong2*)&xr[j0 + 128];
        MICRO_TILE();
    }

    // commit k-half 1
    #pragma unroll
    for (int it = 0; it < 8; it++) {
        int p = it * 256 + tid;
        int c = p >> 6, j4 = p & 63;
        *(float4*)&s_x1[c * 256 + j4 * 4] = st[it];
    }
    __syncthreads();

    #pragma unroll 4
    for (int k = 0; k < 32; k++) {
        const float* wr = &s_w[(k + 32) * 64];
        float4 a0 = *(const float4*)&wr[r];
        float4 a1 = *(const float4*)&wr[r + 4];
        const float* xr = &s_x1[k * 256];
        ulonglong2 b0 = *(const ulonglong2*)&xr[j0];
        ulonglong2 b1 = *(const ulonglong2*)&xr[j0 + 128];
        MICRO_TILE();
    }

    #pragma unroll
    for (int i = 0; i < 8; i++) {
        float bb = s_b[r + i];
        float2 p0 = unpk(acc[i][0]), p1 = unpk(acc[i][1]);
        float2 p2 = unpk(acc[i][2]), p3 = unpk(acc[i][3]);
        float* yr = &Yb[(size_t)(r + i) * Lc + l0];
        *(float4*)&yr[j0]       = make_float4(p0.x - bb, p0.y - bb, p1.x - bb, p1.y - bb);
        *(float4*)&yr[j0 + 128] = make_float4(p2.x - bb, p2.y - bb, p3.x - bb, p3.y - bb);
    }
}

// ================= launch =================
extern "C" void kernel_launch(void* const* d_in, const int* in_sizes, int n_in,
                              void* d_out, int out_size) {
    const float* X = (const float*)d_in[0];
    float* Y = (float*)d_out;

    cudaFuncSetAttribute(apply_kernel, cudaFuncAttributeMaxDynamicSharedMemorySize,
                         APPLY_SMEM);
    cudaFuncSetAttribute(solver_kernel, cudaFuncAttributeMaxDynamicSharedMemorySize,
                         SOLVER_SMEM);

    gram_kernel<<<NBLK_G, 256>>>(X);
    reduce_kernel<<<129, 256>>>();
    solver_kernel<<<1, 256, SOLVER_SMEM>>>();
    apply_kernel<<<NBLK_A, 256, APPLY_SMEM>>>(X, Y);
}

// round 7
// speedup vs baseline: 1.3352x; 1.1233x over previous
#include <cuda_runtime.h>
#include <cstdint>

// Problem constants
#define Bb 32
#define Cc 64
#define Lc 8192
#define Mm (Bb * Lc)            // 262144 columns
#define NBLK 296                // 148 SMs x 2 resident blocks = single balanced wave
#define NT_G 4096               // gram tiles (64 cols each)
#define NT_A 2048               // apply tiles (128 cols each)
#define EPSV 1e-5f

// ---------------- scratch (device globals; no allocation allowed) ----------------
__device__ __align__(16) float g_gram_part[NBLK * 4096];   // 4.85 MB partial Grams
__device__ __align__(16) float g_sum_part[NBLK * 64];
__device__ __align__(16) float g_gram[4096];
__device__ __align__(16) float g_mean[64];
__device__ __align__(16) float g_wmT[4096];                // wmT[k][c] = wm[c][k]
__device__ __align__(16) float g_bias[64];                 // wm @ mean

// ---------------- f32x2 helpers (FFMA2: 2x fp32 FMA throughput) ----------------
__device__ __forceinline__ unsigned long long dup2(float v) {
    unsigned long long r;
    asm("mov.b64 %0, {%1, %1};" : "=l"(r) : "f"(v));
    return r;
}
__device__ __forceinline__ void fma2(unsigned long long& d, unsigned long long a,
                                     unsigned long long b) {
    asm("fma.rn.f32x2 %0, %1, %2, %0;" : "+l"(d) : "l"(a), "l"(b));
}
__device__ __forceinline__ void add2(unsigned long long& d, unsigned long long a) {
    asm("add.rn.f32x2 %0, %0, %1;" : "+l"(d) : "l"(a));
}
__device__ __forceinline__ float2 unpk(unsigned long long v) {
    float2 r;
    asm("mov.b64 {%0, %1}, %2;" : "=f"(r.x), "=f"(r.y) : "l"(v));
    return r;
}
__device__ __forceinline__ uint32_t smem_u32(const void* p) {
    uint32_t a;
    asm("{ .reg .u64 t; cvta.to.shared.u64 t, %1; cvt.u32.u64 %0, t; }"
        : "=r"(a) : "l"(p));
    return a;
}
__device__ __forceinline__ void cpasync16(uint32_t dst, const float* src) {
    asm volatile("cp.async.cg.shared.global [%0], [%1], 16;" :: "r"(dst), "l"(src));
}
#define CP_COMMIT() asm volatile("cp.async.commit_group;" ::: "memory")
#define CP_WAIT(n)  asm volatile("cp.async.wait_group %0;" :: "n"(n) : "memory")

// 8-row x 8-col FFMA2 micro-tile row: b0/b1 = 4 B pairs in scope
#define MICRO_FMA_ROW(ACC, AV)                                          \
    do { unsigned long long _d = dup2(AV);                              \
         fma2(ACC[0], _d, b0.x); fma2(ACC[1], _d, b0.y);                \
         fma2(ACC[2], _d, b1.x); fma2(ACC[3], _d, b1.y); } while (0)

// ================= Kernel 1: per-block partial Gram + channel sums =================
// Grid 296 (one balanced wave at occ 2). Each block accumulates a partial Gram over
// a contiguous range of ~13.8 64-column tiles (flat tile id: batch = tt>>7,
// l = (tt&127)*64). Double-buffered: LDG of tile i+1 in regs while computing tile i.
// Split-k: 4 groups x 64 threads; group g handles k = g*16..+15, 8x8 register tile.
__global__ __launch_bounds__(256, 2) void gram_kernel(const float* __restrict__ X) {
    __shared__ __align__(16) float sT[2][64 * 68];             // [buf][k][c]
    const int tid = threadIdx.x;
    const int bid = blockIdx.x;
    const int ts = (bid * NT_G) / NBLK;
    const int te = ((bid + 1) * NT_G) / NBLK;

    const int crow = tid >> 4;          // 0..15
    const int k4   = tid & 15;
    const int g  = tid >> 6;            // split-k group 0..3
    const int gt = tid & 63;
    const int gy = gt >> 3, gx = gt & 7;
    const int r  = gy * 8;
    const int cc = gx * 8;
    const int kbase = g * 16;

    unsigned long long acc[8][4];
    #pragma unroll
    for (int i = 0; i < 8; i++) { acc[i][0] = acc[i][1] = acc[i][2] = acc[i][3] = 0ull; }
    float cs[4] = {0.f, 0.f, 0.f, 0.f};

    float4 st[4];
    // prefetch + store tile ts
    {
        int bb = ts >> 7, l = (ts & 127) << 6;
        const float* Xb = X + (size_t)bb * Cc * Lc + l;
        #pragma unroll
        for (int it = 0; it < 4; it++)
            st[it] = *(const float4*)&Xb[(size_t)(it * 16 + crow) * Lc + k4 * 4];
        float* dst = &sT[0][0];
        #pragma unroll
        for (int it = 0; it < 4; it++) {
            float4 v = st[it];
            cs[it] += (v.x + v.y) + (v.z + v.w);
            int c = it * 16 + crow, kb = k4 * 4;
            dst[(kb + 0) * 68 + c] = v.x;
            dst[(kb + 1) * 68 + c] = v.y;
            dst[(kb + 2) * 68 + c] = v.z;
            dst[(kb + 3) * 68 + c] = v.w;
        }
    }
    __syncthreads();

    #pragma unroll 1
    for (int i = ts; i < te; i++) {
        const int cur = (i - ts) & 1;
        if (i + 1 < te) {
            int bb = (i + 1) >> 7, l = ((i + 1) & 127) << 6;
            const float* Xb = X + (size_t)bb * Cc * Lc + l;
            #pragma unroll
            for (int it = 0; it < 4; it++)
                st[it] = *(const float4*)&Xb[(size_t)(it * 16 + crow) * Lc + k4 * 4];
        }
        // compute this group's 16 k-steps from sT[cur]
        const float* buf = &sT[cur][0];
        #pragma unroll
        for (int kk = 0; kk < 16; kk++) {
            const float* row = &buf[(kbase + kk) * 68];
            float4 a0 = *(const float4*)&row[r];
            float4 a1 = *(const float4*)&row[r + 4];
            ulonglong2 b0 = *(const ulonglong2*)&row[cc];
            ulonglong2 b1 = *(const ulonglong2*)&row[cc + 4];
            MICRO_FMA_ROW(acc[0], a0.x);
            MICRO_FMA_ROW(acc[1], a0.y);
            MICRO_FMA_ROW(acc[2], a0.z);
            MICRO_FMA_ROW(acc[3], a0.w);
            MICRO_FMA_ROW(acc[4], a1.x);
            MICRO_FMA_ROW(acc[5], a1.y);
            MICRO_FMA_ROW(acc[6], a1.z);
            MICRO_FMA_ROW(acc[7], a1.w);
        }
        if (i + 1 < te) {
            float* dst = &sT[1 - cur][0];
            #pragma unroll
            for (int it = 0; it < 4; it++) {
                float4 v = st[it];
                cs[it] += (v.x + v.y) + (v.z + v.w);
                int c = it * 16 + crow, kb = k4 * 4;
                dst[(kb + 0) * 68 + c] = v.x;
                dst[(kb + 1) * 68 + c] = v.y;
                dst[(kb + 2) * 68 + c] = v.z;
                dst[(kb + 3) * 68 + c] = v.w;
            }
        }
        __syncthreads();
    }

    // cross-group reduction (aliases the now-dead tile buffers; deterministic)
    unsigned long long* red2 = (unsigned long long*)&sT[0][0];   // 16 KB
    #pragma unroll 1
    for (int gg = 1; gg < 4; gg++) {
        if (g == gg) {
            #pragma unroll
            for (int i = 0; i < 8; i++) {
                unsigned long long* d = &red2[(r + i) * 32 + gx * 4];
                d[0] = acc[i][0]; d[1] = acc[i][1];
                d[2] = acc[i][2]; d[3] = acc[i][3];
            }
        }
        __syncthreads();
        if (g == 0) {
            #pragma unroll
            for (int i = 0; i < 8; i++) {
                const unsigned long long* s2 = &red2[(r + i) * 32 + gx * 4];
                add2(acc[i][0], s2[0]); add2(acc[i][1], s2[1]);
                add2(acc[i][2], s2[2]); add2(acc[i][3], s2[3]);
            }
        }
        __syncthreads();
    }

    if (g == 0) {
        float* gp = g_gram_part + (size_t)bid * 4096;
        #pragma unroll
        for (int i = 0; i < 8; i++) {
            float2 p0 = unpk(acc[i][0]), p1 = unpk(acc[i][1]);
            float2 p2 = unpk(acc[i][2]), p3 = unpk(acc[i][3]);
            *(float4*)&gp[(r + i) * 64 + cc]     = make_float4(p0.x, p0.y, p1.x, p1.y);
            *(float4*)&gp[(r + i) * 64 + cc + 4] = make_float4(p2.x, p2.y, p3.x, p3.y);
        }
    }

    // channel sums: reduce across the 16 lanes sharing (it, crow) via shfl
    #pragma unroll
    for (int it = 0; it < 4; it++) {
        float v = cs[it];
        v += __shfl_down_sync(0xffffffffu, v, 8, 16);
        v += __shfl_down_sync(0xffffffffu, v, 4, 16);
        v += __shfl_down_sync(0xffffffffu, v, 2, 16);
        v += __shfl_down_sync(0xffffffffu, v, 1, 16);
        if (k4 == 0) g_sum_part[bid * 64 + it * 16 + crow] = v;
    }
}

// ================= Kernel 2: deterministic reduction of partials =================
// 129 blocks. Blocks 0..127: 32 Gram elements each (coalesced over e), 8 chunks of
// 37 partials per thread-warp-slice. Block 128: channel sums -> mean.
__global__ __launch_bounds__(256) void reduce_kernel() {
    __shared__ float s[256];
    const int tid = threadIdx.x;
    if (blockIdx.x < 128) {
        const int e = blockIdx.x * 32 + (tid & 31);
        const int ch = tid >> 5;                           // 0..7, 37 partials each
        const float* base = g_gram_part + (size_t)(ch * 37) * 4096 + e;
        float a0 = 0, a1 = 0, a2 = 0, a3 = 0;
        #pragma unroll 1
        for (int q = 0; q < 36; q += 4) {
            a0 += base[(size_t)(q + 0) * 4096];
            a1 += base[(size_t)(q + 1) * 4096];
            a2 += base[(size_t)(q + 2) * 4096];
            a3 += base[(size_t)(q + 3) * 4096];
        }
        a0 += base[(size_t)36 * 4096];
        s[tid] = (a0 + a1) + (a2 + a3);
        __syncthreads();
        if (tid < 32) {
            float r = 0.f;
            #pragma unroll
            for (int ch2 = 0; ch2 < 8; ch2++) r += s[ch2 * 32 + tid];
            g_gram[blockIdx.x * 32 + tid] = r;
        }
    } else {
        const int c = tid & 63, ch = tid >> 6;             // 4 chunks x 74 partials
        const float* base = g_sum_part + (size_t)(ch * 74) * 64 + c;
        float a0 = 0, a1 = 0;
        #pragma unroll 1
        for (int q = 0; q < 74; q += 2) {
            a0 += base[(q + 0) * 64];
            a1 += base[(q + 1) * 64];
        }
        s[tid] = a0 + a1;
        __syncthreads();
        if (tid < 64) {
            float r = (s[tid] + s[64 + tid]) + (s[128 + tid] + s[192 + tid]);
            g_mean[tid] = r * (1.0f / (float)Mm);
        }
    }
}

// ================= Kernel 3: Sigma + Newton-Schulz (single block) =================
// Per iteration: phase A computes U = P*P and V = P*S CONCURRENTLY (shared A-loads,
// 2x ILP on the FMA pipe), phase B computes W = U*V with the P-update fused into its
// epilogue. 2 syncs per iteration.
#define SOLVER_SMEM (4 * 4096 * (int)sizeof(float))

__global__ __launch_bounds__(256) void solver_kernel() {
    extern __shared__ float ssm[];
    float* P = ssm;
    float* S = ssm + 4096;
    float* U = ssm + 8192;
    float* V = ssm + 12288;
    const int tid = threadIdx.x;
    const float inv_m = 1.0f / (float)Mm;

    // Sigma = eps*I + G/m - mean*mean^T
    for (int e = tid; e < 4096; e += 256) {
        int c1 = e >> 6, c2 = e & 63;
        S[e] = g_gram[e] * inv_m - g_mean[c1] * g_mean[c2] + ((c1 == c2) ? EPSV : 0.0f);
    }
    __syncthreads();

    // every thread computes the trace (broadcast reads; bitwise identical)
    float tr = 0.f;
    #pragma unroll
    for (int c = 0; c < 64; c++) tr += S[c * 65];
    const float rTr = 1.0f / tr;
    __syncthreads();

    for (int e = tid; e < 4096; e += 256) {
        S[e] *= rTr;
        int c1 = e >> 6, c2 = e & 63;
        P[e] = (c1 == c2) ? 1.0f : 0.0f;
    }
    __syncthreads();

    const int ty = tid >> 4, tx = tid & 15;
    const int r = ty * 4, cb = tx * 4;

    #pragma unroll 1
    for (int it = 0; it < 5; it++) {
        // ---- phase A: U = P*P and V = P*S, shared A-loads ----
        unsigned long long aU[4][2] = {}, aV[4][2] = {};
        #pragma unroll
        for (int k4 = 0; k4 < 16; k4++) {
            float4 a0 = *(const float4*)&P[(r + 0) * 64 + k4 * 4];
            float4 a1 = *(const float4*)&P[(r + 1) * 64 + k4 * 4];
            float4 a2 = *(const float4*)&P[(r + 2) * 64 + k4 * 4];
            float4 a3 = *(const float4*)&P[(r + 3) * 64 + k4 * 4];
            #pragma unroll
            for (int kk = 0; kk < 4; kk++) {
                float f0 = kk == 0 ? a0.x : kk == 1 ? a0.y : kk == 2 ? a0.z : a0.w;
                float f1 = kk == 0 ? a1.x : kk == 1 ? a1.y : kk == 2 ? a1.z : a1.w;
                float f2 = kk == 0 ? a2.x : kk == 1 ? a2.y : kk == 2 ? a2.z : a2.w;
                float f3 = kk == 0 ? a3.x : kk == 1 ? a3.y : kk == 2 ? a3.z : a3.w;
                const int k = k4 * 4 + kk;
                ulonglong2 bp = *(const ulonglong2*)&P[k * 64 + cb];
                ulonglong2 bs = *(const ulonglong2*)&S[k * 64 + cb];
                unsigned long long d;
                d = dup2(f0);
                fma2(aU[0][0], d, bp.x); fma2(aU[0][1], d, bp.y);
                fma2(aV[0][0], d, bs.x); fma2(aV[0][1], d, bs.y);
                d = dup2(f1);
                fma2(aU[1][0], d, bp.x); fma2(aU[1][1], d, bp.y);
                fma2(aV[1][0], d, bs.x); fma2(aV[1][1], d, bs.y);
                d = dup2(f2);
                fma2(aU[2][0], d, bp.x); fma2(aU[2][1], d, bp.y);
                fma2(aV[2][0], d, bs.x); fma2(aV[2][1], d, bs.y);
                d = dup2(f3);
                fma2(aU[3][0], d, bp.x); fma2(aU[3][1], d, bp.y);
                fma2(aV[3][0], d, bs.x); fma2(aV[3][1], d, bs.y);
            }
        }
        #pragma unroll
        for (int i = 0; i < 4; i++) {
            float2 u0 = unpk(aU[i][0]), u1 = unpk(aU[i][1]);
            float2 v0 = unpk(aV[i][0]), v1 = unpk(aV[i][1]);
            *(float4*)&U[(r + i) * 64 + cb] = make_float4(u0.x, u0.y, u1.x, u1.y);
            *(float4*)&V[(r + i) * 64 + cb] = make_float4(v0.x, v0.y, v1.x, v1.y);
        }
        __syncthreads();

        // ---- phase B: W = U*V, P = 1.5P - 0.5W fused ----
        unsigned long long aW[4][2] = {};
        #pragma unroll
        for (int k4 = 0; k4 < 16; k4++) {
            float4 a0 = *(const float4*)&U[(r + 0) * 64 + k4 * 4];
            float4 a1 = *(const float4*)&U[(r + 1) * 64 + k4 * 4];
            float4 a2 = *(const float4*)&U[(r + 2) * 64 + k4 * 4];
            float4 a3 = *(const float4*)&U[(r + 3) * 64 + k4 * 4];
            #pragma unroll
            for (int kk = 0; kk < 4; kk++) {
                float f0 = kk == 0 ? a0.x : kk == 1 ? a0.y : kk == 2 ? a0.z : a0.w;
                float f1 = kk == 0 ? a1.x : kk == 1 ? a1.y : kk == 2 ? a1.z : a1.w;
                float f2 = kk == 0 ? a2.x : kk == 1 ? a2.y : kk == 2 ? a2.z : a2.w;
                float f3 = kk == 0 ? a3.x : kk == 1 ? a3.y : kk == 2 ? a3.z : a3.w;
                ulonglong2 bv = *(const ulonglong2*)&V[(k4 * 4 + kk) * 64 + cb];
                unsigned long long d;
                d = dup2(f0); fma2(aW[0][0], d, bv.x); fma2(aW[0][1], d, bv.y);
                d = dup2(f1); fma2(aW[1][0], d, bv.x); fma2(aW[1][1], d, bv.y);
                d = dup2(f2); fma2(aW[2][0], d, bv.x); fma2(aW[2][1], d, bv.y);
                d = dup2(f3); fma2(aW[3][0], d, bv.x); fma2(aW[3][1], d, bv.y);
            }
        }
        #pragma unroll
        for (int i = 0; i < 4; i++) {
            float2 w0 = unpk(aW[i][0]), w1 = unpk(aW[i][1]);
            float* pr = &P[(r + i) * 64 + cb];
            float4 pv = *(float4*)pr;
            *(float4*)pr = make_float4(1.5f * pv.x - 0.5f * w0.x,
                                       1.5f * pv.y - 0.5f * w0.y,
                                       1.5f * pv.z - 0.5f * w1.x,
                                       1.5f * pv.w - 0.5f * w1.y);
        }
        __syncthreads();
    }

    const float sq = sqrtf(rTr);
    for (int e = tid; e < 4096; e += 256) {
        int c = e >> 6, cp = e & 63;
        g_wmT[cp * 64 + c] = P[e] * sq;
    }
    if (tid < 64) {
        float bs = 0.f;
        #pragma unroll 8
        for (int cp = 0; cp < 64; cp++) bs += P[tid * 64 + cp] * g_mean[cp];
        g_bias[tid] = bs * sq;
    }
}

// ================= Kernel 4: apply  Y = wm @ X - bias =================
// Grid 296 (one balanced wave at occ 2). Each block loops over ~6.9 128-column
// tiles (flat tile id: batch = tt>>6, l = (tt&63)*128), cp.async double-buffered:
// next tile's global->shared copy runs under the current tile's FMA phase.
// 8x4 per-thread tile: warp w owns rows w*8..+7 (broadcast A), lane owns cols
// lane*4..+3 (contiguous LDS.128). wm + bias loaded once per block.
#define APPLY_SMEM ((4096 + 2 * 8192 + 64) * (int)sizeof(float))

__global__ __launch_bounds__(256, 2) void apply_kernel(const float* __restrict__ X,
                                                       float* __restrict__ Y) {
    extern __shared__ float sm[];
    float* s_w = sm;                     // wmT[k][c]              16 KB
    float* s_x = sm + 4096;              // 2 x [64][128] tiles    64 KB
    float* s_b = sm + 4096 + 16384;      // bias
    const int tid = threadIdx.x;
    const int bid = blockIdx.x;
    const int ts = (bid * NT_A) / NBLK;
    const int te = ((bid + 1) * NT_A) / NBLK;

    // wm + bias (once per block)
    #pragma unroll
    for (int itw = 0; itw < 4; itw++) {
        int p = itw * 256 + tid;
        *(float4*)&s_w[p * 4] = *(const float4*)&g_wmT[p * 4];
    }
    if (tid < 64) s_b[tid] = g_bias[tid];

    const uint32_t sx_base = smem_u32(s_x);
    const int c8  = tid >> 5;            // thread's copy rows: c = itc*8 + c8
    const int j4  = tid & 31;            // float4 column within 128-col tile

    // prefetch tile ts into buffer 0
    {
        int bb = ts >> 6, l = (ts & 63) << 7;
        const float* Xb = X + (size_t)bb * Cc * Lc + l + j4 * 4;
        #pragma unroll
        for (int itc = 0; itc < 8; itc++) {
            int c = itc * 8 + c8;
            cpasync16(sx_base + (uint32_t)(c * 128 + j4 * 4) * 4,
                      Xb + (size_t)c * Lc);
        }
        CP_COMMIT();
    }

    const int w = tid >> 5, lane = tid & 31;
    const int r = w * 8, j0 = lane * 4;

    #pragma unroll 1
    for (int i = ts; i < te; i++) {
        const int cur = (i - ts) & 1;
        if (i + 1 < te) {
            int bb = (i + 1) >> 6, l = ((i + 1) & 63) << 7;
            const float* Xb = X + (size_t)bb * Cc * Lc + l + j4 * 4;
            const uint32_t dst0 = sx_base + (uint32_t)((1 - cur) * 8192) * 4;
            #pragma unroll
            for (int itc = 0; itc < 8; itc++) {
                int c = itc * 8 + c8;
                cpasync16(dst0 + (uint32_t)(c * 128 + j4 * 4) * 4,
                          Xb + (size_t)c * Lc);
            }
            CP_COMMIT();
            CP_WAIT(1);                  // tile i complete, tile i+1 in flight
        } else {
            CP_WAIT(0);
        }
        __syncthreads();

        const float* xb = s_x + cur * 8192;
        unsigned long long acc[8][2];
        #pragma unroll
        for (int q = 0; q < 8; q++) { acc[q][0] = acc[q][1] = 0ull; }

        #pragma unroll 8
        for (int k = 0; k < 64; k++) {
            const float* wr = &s_w[k * 64];
            float4 a0 = *(const float4*)&wr[r];
            float4 a1 = *(const float4*)&wr[r + 4];
            ulonglong2 b2 = *(const ulonglong2*)&xb[k * 128 + j0];
            unsigned long long d;
            d = dup2(a0.x); fma2(acc[0][0], d, b2.x); fma2(acc[0][1], d, b2.y);
            d = dup2(a0.y); fma2(acc[1][0], d, b2.x); fma2(acc[1][1], d, b2.y);
            d = dup2(a0.z); fma2(acc[2][0], d, b2.x); fma2(acc[2][1], d, b2.y);
            d = dup2(a0.w); fma2(acc[3][0], d, b2.x); fma2(acc[3][1], d, b2.y);
            d = dup2(a1.x); fma2(acc[4][0], d, b2.x); fma2(acc[4][1], d, b2.y);
            d = dup2(a1.y); fma2(acc[5][0], d, b2.x); fma2(acc[5][1], d, b2.y);
            d = dup2(a1.z); fma2(acc[6][0], d, b2.x); fma2(acc[6][1], d, b2.y);
            d = dup2(a1.w); fma2(acc[7][0], d, b2.x); fma2(acc[7][1], d, b2.y);
        }

        {
            int bb = i >> 6, l = (i & 63) << 7;
            float* Yb = Y + (size_t)bb * Cc * Lc + l + j0;
            #pragma unroll
            for (int q = 0; q < 8; q++) {
                float bbv = s_b[r + q];
                float2 p0 = unpk(acc[q][0]), p1 = unpk(acc[q][1]);
                *(float4*)&Yb[(size_t)(r + q) * Lc] =
                    make_float4(p0.x - bbv, p0.y - bbv, p1.x - bbv, p1.y - bbv);
            }
        }
        __syncthreads();   // all reads of buf cur done before next prefetch overwrites
    }
}

// ================= launch =================
extern "C" void kernel_launch(void* const* d_in, const int* in_sizes, int n_in,
                              void* d_out, int out_size) {
    const float* X = (const float*)d_in[0];
    float* Y = (float*)d_out;

    cudaFuncSetAttribute(apply_kernel, cudaFuncAttributeMaxDynamicSharedMemorySize,
                         APPLY_SMEM);
    cudaFuncSetAttribute(solver_kernel, cudaFuncAttributeMaxDynamicSharedMemorySize,
                         SOLVER_SMEM);

    gram_kernel<<<NBLK, 256>>>(X);
    reduce_kernel<<<129, 256>>>();
    solver_kernel<<<1, 256, SOLVER_SMEM>>>();
    apply_kernel<<<NBLK, 256, APPLY_SMEM>>>(X, Y);
}